// round 15
// baseline (speedup 1.0000x reference)
#include <cuda_runtime.h>
#include <cuda_fp16.h>
#include <cstdint>
#include <math.h>

#define N_ROWS 32768
#define DIM    64
#define NEMB   8192

// ---- output layout (concatenated reference tuple, all float32) ----
#define OFF_Q    0
#define OFF_LOSS 2097152
#define OFF_IDX  2097153
#define OFF_PERP 2129921
#define OFF_W    2129922
#define OFF_CC   2654210
#define OFF_WS   2662402

// ---- argmin tiling ----
#define RPB   128            // rows per block (M)
#define CPC   128            // codes per chunk (N)
#define NCH   (NEMB/CPC)     // 64 chunks
#define NTHR  512            // 16 warps: 4(M) x 4(N)

// SMEM layout (bytes). Tiles: 128 rows x 128B (64 fp16), XOR-swizzled.
#define A_OFF      0                      // 2 x 16KB (h,m splits of x rows)
#define B_OFF      32768                  // 2 bufs x 2 x 16KB
#define SEN_OFF    98304                  // 2 x 512B
#define RED_OFF    99328                  // 128 rows x 4 warpcols x 16B
#define SMEM_BYTES 107520

// ---- device scratch ----
__device__ int   g_idx[N_ROWS];
__device__ float g_counts[NEMB];
__device__ float g_embsum[NEMB * DIM];
__device__ float g_enormh[NEMB];
__device__ float g_nsum;
__device__ float g_loss;
__device__ float g_plogp;
__device__ int   g_nfix;
__device__ int   g_fixlist[N_ROWS];
// pre-split codebook (2-term fp16 decomposition of w)
__device__ __half g_wh[NEMB * DIM];
__device__ __half g_wm[NEMB * DIM];

// ================= helpers =================
__device__ __forceinline__ uint32_t smem_u32_of(const void* p) {
    uint32_t a;
    asm("{ .reg .u64 t; cvta.to.shared.u64 t, %1; cvt.u32.u64 %0, t; }"
        : "=r"(a) : "l"(p));
    return a;
}
__device__ __forceinline__ void ldmx4(uint32_t& r0, uint32_t& r1, uint32_t& r2,
                                      uint32_t& r3, uint32_t a) {
    asm volatile("ldmatrix.sync.aligned.m8n8.x4.shared.b16 {%0,%1,%2,%3}, [%4];"
                 : "=r"(r0), "=r"(r1), "=r"(r2), "=r"(r3) : "r"(a));
}
__device__ __forceinline__ void mma16816(float& c0, float& c1, float& c2, float& c3,
                                         uint32_t a0, uint32_t a1, uint32_t a2, uint32_t a3,
                                         uint32_t b0, uint32_t b1) {
    asm volatile("mma.sync.aligned.m16n8k16.row.col.f32.f16.f16.f32 "
                 "{%0,%1,%2,%3}, {%4,%5,%6,%7}, {%8,%9}, {%0,%1,%2,%3};"
                 : "+f"(c0), "+f"(c1), "+f"(c2), "+f"(c3)
                 : "r"(a0), "r"(a1), "r"(a2), "r"(a3), "r"(b0), "r"(b1));
}
__device__ __forceinline__ void cp16(uint32_t dst, const void* src) {
    asm volatile("cp.async.cg.shared.global [%0], [%1], 16;" :: "r"(dst), "l"(src));
}
#define CP_COMMIT() asm volatile("cp.async.commit_group;" ::: "memory")
#define CP_WAIT0()  asm volatile("cp.async.wait_group 0;" ::: "memory")

__device__ __forceinline__ uint32_t pack_h2(__half a, __half b) {
    unsigned short ua = *(unsigned short*)&a, ub = *(unsigned short*)&b;
    return (uint32_t)ua | ((uint32_t)ub << 16);
}
__device__ __forceinline__ unsigned long long pack_key(float s, int j) {
    uint32_t u = __float_as_uint(s);
    u = (u & 0x80000000u) ? ~u : (u | 0x80000000u);   // order-preserving
    return ((unsigned long long)u << 32) | (uint32_t)(~j);  // bigger = better; ties -> smaller j
}

// ============================================================
__global__ void k_init() {
    int t = blockIdx.x * 256 + threadIdx.x;
    if (t < NEMB * DIM) g_embsum[t] = 0.f;
    if (t < NEMB)       g_counts[t] = 0.f;
    if (t == 0) { g_nsum = 0.f; g_loss = 0.f; g_plogp = 0.f; g_nfix = 0; }
}

// 2-way fp16 split of the codebook
__global__ void k_prep(const float* __restrict__ w) {
    int t = blockIdx.x * 256 + threadIdx.x;
    float v = w[t];
    __half h = __float2half_rn(v);
    __half m = __float2half_rn(v - __half2float(h));
    g_wh[t] = h; g_wm[t] = m;
}

__global__ void k_enorm(const float* __restrict__ w) {
    int code = blockIdx.x * 8 + (threadIdx.x >> 5);
    int lane = threadIdx.x & 31;
    float a = w[code * DIM + lane];
    float b = w[code * DIM + 32 + lane];
    float s = a * a + b * b;
#pragma unroll
    for (int m = 16; m >= 1; m >>= 1) s += __shfl_xor_sync(0xffffffffu, s, m);
    if (lane == 0) g_enormh[code] = 0.5f * s;
}

// ============================================================
// fp16 2-split tensor-core argmin (products hh + hm + mh).
// Per-row second-best tracked with IDENTITY-AWARE merges (the
// R14 butterfly double-counted the max as second-best, flagging
// every row for exact repair); rows with top-2 gap < 1e-3 go to
// exact f32 repair in k_fix.
// ============================================================
__device__ __forceinline__ void prefetch_chunk(uint32_t sb, int buf, int cbase, int tid) {
#pragma unroll
    for (int i = 0; i < 4; i++) {
        int u = tid + i * NTHR;               // 2 splits * 128 rows * 8 col16 = 2048
        int s = u >> 10;
        int rem = u & 1023;
        int row = rem >> 3, c16 = rem & 7;
        uint32_t dst = sb + B_OFF + buf * 32768 + s * 16384 +
                       row * 128 + (((uint32_t)(c16 ^ (row & 7))) << 4);
        const __half* wsp = (s == 0) ? g_wh : g_wm;
        cp16(dst, wsp + (size_t)(cbase + row) * 64 + c16 * 8);
    }
    if (tid >= NTHR - 32) {                   // sen: 128 floats = 32 x 16B
        int u = tid - (NTHR - 32);
        cp16(sb + SEN_OFF + buf * 512 + u * 16, g_enormh + cbase + u * 4);
    }
    CP_COMMIT();
}

__global__ void __launch_bounds__(NTHR, 1) k_argmin_mma(const float* __restrict__ x,
                                                        float* __restrict__ out_idxf) {
    extern __shared__ __align__(16) char smem[];
    uint32_t sb = smem_u32_of(smem);
    int tid = threadIdx.x;
    int wid = tid >> 5;
    int lid = tid & 31;
    int rowBase = blockIdx.x * RPB;

    int wr = wid & 3;          // M slab (32 rows)
    int wc = wid >> 2;         // N slab (32 codes)
    int Mbase = wr * 32;
    int Nbase = wc * 32;

    // ldmatrix lane geometry (same for A and B)
    int ri    = lid & 7;
    int mi    = lid >> 3;
    int rowIn = (mi & 1) * 8 + ri;   // row within 16-row tile
    int half  = mi >> 1;             // col16 half within tile
    uint32_t colk[4];
#pragma unroll
    for (int kt = 0; kt < 4; kt++) colk[kt] = (uint32_t)((kt * 2 + half) ^ ri) << 4;
    uint32_t aLane = sb + A_OFF + (uint32_t)(Mbase + rowIn) * 128;
    uint32_t bLane = sb + B_OFF + (uint32_t)(Nbase + rowIn) * 128;

    // kick off B prefetch for chunk 0
    prefetch_chunk(sb, 0, 0, tid);

    // ---- A fill: split 128x64 f32 rows into 2 swizzled fp16 tiles ----
#pragma unroll
    for (int i = 0; i < 2; i++) {
        int u = tid + i * NTHR;              // 128 rows * 8 col16 = 1024
        int row = u >> 3, c16 = u & 7;
        const float* src = x + (size_t)(rowBase + row) * 64 + c16 * 8;
        float4 f0 = *(const float4*)src;
        float4 f1 = *(const float4*)(src + 4);
        float v[8] = {f0.x, f0.y, f0.z, f0.w, f1.x, f1.y, f1.z, f1.w};
        __half hb[8], mb[8];
#pragma unroll
        for (int j = 0; j < 8; j++) {
            __half h = __float2half_rn(v[j]);
            hb[j] = h;
            mb[j] = __float2half_rn(v[j] - __half2float(h));
        }
        uint32_t off = (uint32_t)row * 128 + (((uint32_t)(c16 ^ (row & 7))) << 4);
        uint4 ph = make_uint4(pack_h2(hb[0], hb[1]), pack_h2(hb[2], hb[3]),
                              pack_h2(hb[4], hb[5]), pack_h2(hb[6], hb[7]));
        uint4 pm = make_uint4(pack_h2(mb[0], mb[1]), pack_h2(mb[2], mb[3]),
                              pack_h2(mb[4], mb[5]), pack_h2(mb[6], mb[7]));
        *(uint4*)(smem + A_OFF + off)         = ph;
        *(uint4*)(smem + A_OFF + 16384 + off) = pm;
    }
    __syncthreads();

    // ---- A fragments register-resident (2 splits x 2 mt x 4 kt x 4) ----
    uint32_t afr[2][2][4][4];
#pragma unroll
    for (int s = 0; s < 2; s++)
#pragma unroll
        for (int mt = 0; mt < 2; mt++)
#pragma unroll
            for (int kt = 0; kt < 4; kt++)
                ldmx4(afr[s][mt][kt][0], afr[s][mt][kt][1],
                      afr[s][mt][kt][2], afr[s][mt][kt][3],
                      aLane + s * 16384 + mt * 2048 + colk[kt]);

    CP_WAIT0();
    __syncthreads();

    float best[4], best2[4];
    int   bi[4];
#pragma unroll
    for (int k = 0; k < 4; k++) { best[k] = -3.402823466e38f; best2[k] = -3.402823466e38f; bi[k] = 0; }

    for (int ch = 0; ch < NCH; ++ch) {
        int db = ch & 1;
        if (ch + 1 < NCH) prefetch_chunk(sb, db ^ 1, (ch + 1) * CPC, tid);

        uint32_t bB = bLane + db * 32768;
        const float* senp = (const float*)(smem + SEN_OFF + db * 512);

#pragma unroll
        for (int hh = 0; hh < 2; hh++) {     // 16-code N-half
            float acc[2][2][4];
#pragma unroll
            for (int mt = 0; mt < 2; mt++)
#pragma unroll
                for (int nt = 0; nt < 2; nt++)
#pragma unroll
                    for (int q = 0; q < 4; q++) acc[mt][nt][q] = 0.f;

            uint32_t bh = bB + hh * 2048;
            // B = h split: products hh (A=h) and mh (A=m)
#pragma unroll
            for (int kt = 0; kt < 4; kt++) {
                uint32_t b0, b1, b2, b3;
                ldmx4(b0, b1, b2, b3, bh + colk[kt]);
#pragma unroll
                for (int mt = 0; mt < 2; mt++) {
                    mma16816(acc[mt][0][0], acc[mt][0][1], acc[mt][0][2], acc[mt][0][3],
                             afr[0][mt][kt][0], afr[0][mt][kt][1],
                             afr[0][mt][kt][2], afr[0][mt][kt][3], b0, b2);
                    mma16816(acc[mt][1][0], acc[mt][1][1], acc[mt][1][2], acc[mt][1][3],
                             afr[0][mt][kt][0], afr[0][mt][kt][1],
                             afr[0][mt][kt][2], afr[0][mt][kt][3], b1, b3);
                }
#pragma unroll
                for (int mt = 0; mt < 2; mt++) {
                    mma16816(acc[mt][0][0], acc[mt][0][1], acc[mt][0][2], acc[mt][0][3],
                             afr[1][mt][kt][0], afr[1][mt][kt][1],
                             afr[1][mt][kt][2], afr[1][mt][kt][3], b0, b2);
                    mma16816(acc[mt][1][0], acc[mt][1][1], acc[mt][1][2], acc[mt][1][3],
                             afr[1][mt][kt][0], afr[1][mt][kt][1],
                             afr[1][mt][kt][2], afr[1][mt][kt][3], b1, b3);
                }
            }
            // B = m split: product hm (A=h)
#pragma unroll
            for (int kt = 0; kt < 4; kt++) {
                uint32_t b0, b1, b2, b3;
                ldmx4(b0, b1, b2, b3, bh + 16384 + colk[kt]);
#pragma unroll
                for (int mt = 0; mt < 2; mt++) {
                    mma16816(acc[mt][0][0], acc[mt][0][1], acc[mt][0][2], acc[mt][0][3],
                             afr[0][mt][kt][0], afr[0][mt][kt][1],
                             afr[0][mt][kt][2], afr[0][mt][kt][3], b0, b2);
                    mma16816(acc[mt][1][0], acc[mt][1][1], acc[mt][1][2], acc[mt][1][3],
                             afr[0][mt][kt][0], afr[0][mt][kt][1],
                             afr[0][mt][kt][2], afr[0][mt][kt][3], b1, b3);
                }
            }

            // ---- epilogue for this half: argmax + second best ----
#define UPD(S, J, R)                                                          \
            { if ((S) > best[R]) { best2[R] = best[R]; best[R] = (S); bi[R] = (J); } \
              else if ((S) > best2[R]) best2[R] = (S); }
#pragma unroll
            for (int nt = 0; nt < 2; nt++) {
                int nl = Nbase + hh * 16 + nt * 8 + (lid & 3) * 2;
                float2 se = *(const float2*)(senp + nl);
                int jb = ch * CPC + nl;
#pragma unroll
                for (int mt = 0; mt < 2; mt++) {
                    float s0 = acc[mt][nt][0] - se.x;
                    float s1 = acc[mt][nt][1] - se.y;
                    float s2 = acc[mt][nt][2] - se.x;
                    float s3 = acc[mt][nt][3] - se.y;
                    int r0 = mt * 2, r1 = mt * 2 + 1;
                    UPD(s0, jb, r0); UPD(s1, jb + 1, r0);
                    UPD(s2, jb, r1); UPD(s3, jb + 1, r1);
                }
            }
#undef UPD
        }

        if (ch + 1 < NCH) CP_WAIT0();
        __syncthreads();
    }

    // ---- merge (b1, idx, b2) across the 4 lanes sharing each row ----
    // IDENTITY-AWARE: after step 1 both lanes hold the same champion;
    // merging it again must not pollute best2 (R14 bug: every row
    // ended up flagged as a near-tie -> full exact re-argmin).
#pragma unroll
    for (int m = 1; m <= 2; m <<= 1) {
#pragma unroll
        for (int rs = 0; rs < 4; rs++) {
            float ob1 = __shfl_xor_sync(0xffffffffu, best[rs],  m);
            int   oi  = __shfl_xor_sync(0xffffffffu, bi[rs],    m);
            float ob2 = __shfl_xor_sync(0xffffffffu, best2[rs], m);
            if (oi == bi[rs]) {
                best2[rs] = fmaxf(best2[rs], ob2);      // same champion: only its runner-up
            } else if (ob1 > best[rs] || (ob1 == best[rs] && oi < bi[rs])) {
                best2[rs] = fmaxf(best[rs], ob2);
                best[rs] = ob1; bi[rs] = oi;
            } else {
                best2[rs] = fmaxf(best2[rs], ob1);
            }
        }
    }
    float4* red = (float4*)(smem + RED_OFF);
    if ((lid & 3) == 0) {
#pragma unroll
        for (int rs = 0; rs < 4; rs++) {
            int mt = rs >> 1, h = rs & 1;
            int row = Mbase + mt * 16 + (lid >> 2) + h * 8;   // row within block
            red[row * 4 + wc] = make_float4(best[rs], __int_as_float(bi[rs]), best2[rs], 0.f);
        }
    }
    __syncthreads();
    if (tid < RPB) {
        float4 v = red[tid * 4];
        float b1 = v.x, b2 = v.z;
        int   i1 = __float_as_int(v.y);
#pragma unroll
        for (int c = 1; c < 4; c++) {
            float4 o = red[tid * 4 + c];
            float o1 = o.x, o2 = o.z;
            int   oi = __float_as_int(o.y);
            if (oi == i1) { b2 = fmaxf(b2, o2); }
            else if (o1 > b1 || (o1 == b1 && oi < i1)) { b2 = fmaxf(b1, o2); b1 = o1; i1 = oi; }
            else b2 = fmaxf(b2, o1);
        }
        int row = rowBase + tid;
        g_idx[row] = i1;
        out_idxf[row] = (float)i1;
        if (b1 - b2 < 1e-3f) {                 // near-tie: exact repair
            int p = atomicAdd(&g_nfix, 1);
            g_fixlist[p] = row;
        }
    }
}

// ============================================================
// exact f32 argmin repair for flagged near-tie rows
// ============================================================
__global__ void k_fix(const float* __restrict__ x, const float* __restrict__ w,
                      float* __restrict__ out_idxf) {
    __shared__ float xs[DIM];
    __shared__ unsigned long long rk[8];
    int nfix = g_nfix;
    for (int f = blockIdx.x; f < nfix; f += gridDim.x) {
        int row = g_fixlist[f];
        if (threadIdx.x < DIM) xs[threadIdx.x] = x[(size_t)row * DIM + threadIdx.x];
        __syncthreads();
        unsigned long long bk = 0;
        for (int c = threadIdx.x; c < NEMB; c += 256) {
            const float* e = w + (size_t)c * DIM;
            float dot = 0.f;
#pragma unroll 16
            for (int d = 0; d < DIM; d++) dot = fmaf(xs[d], e[d], dot);
            unsigned long long k = pack_key(dot - g_enormh[c], c);
            if (k > bk) bk = k;
        }
#pragma unroll
        for (int m = 16; m >= 1; m >>= 1) {
            unsigned long long o = __shfl_xor_sync(0xffffffffu, bk, m);
            if (o > bk) bk = o;
        }
        int wi = threadIdx.x >> 5;
        if ((threadIdx.x & 31) == 0) rk[wi] = bk;
        __syncthreads();
        if (threadIdx.x == 0) {
            unsigned long long k = rk[0];
            for (int i = 1; i < 8; i++) if (rk[i] > k) k = rk[i];
            int idx = (int)(uint32_t)(~(uint32_t)k);
            g_idx[row] = idx;
            out_idxf[row] = (float)idx;
        }
        __syncthreads();
    }
}

// ============================================================
__global__ void k_scatter(const float* __restrict__ x) {
    int t = blockIdx.x * 256 + threadIdx.x;
    if (t >= N_ROWS * DIM) return;
    int n = t >> 6, d = t & 63;
    int idx = g_idx[n];
    atomicAdd(&g_embsum[idx * DIM + d], x[t]);
    if (d == 0) atomicAdd(&g_counts[idx], 1.0f);
}

// ============================================================
__global__ void k_cc(const float* __restrict__ cc_in, float* __restrict__ out_cc) {
    int k = blockIdx.x * 256 + threadIdx.x;
    float c = g_counts[k];
    float ncc = cc_in[k] * 0.99f + 0.01f * c;
    out_cc[k] = ncc;
    float p = c * (1.0f / 32768.0f);
    float pl = p * logf(p + 1e-10f);
#pragma unroll
    for (int m = 16; m >= 1; m >>= 1) {
        ncc += __shfl_xor_sync(0xffffffffu, ncc, m);
        pl  += __shfl_xor_sync(0xffffffffu, pl, m);
    }
    __shared__ float s1[8], s2[8];
    int wi = threadIdx.x >> 5, lane = threadIdx.x & 31;
    if (lane == 0) { s1[wi] = ncc; s2[wi] = pl; }
    __syncthreads();
    if (threadIdx.x == 0) {
        float a = 0.f, b = 0.f;
        for (int i = 0; i < 8; i++) { a += s1[i]; b += s2[i]; }
        atomicAdd(&g_nsum, a);
        atomicAdd(&g_plogp, b);
    }
}

// ============================================================
__global__ void k_weight(const float* __restrict__ ws_in, const float* __restrict__ out_cc,
                         float* __restrict__ out_ws, float* __restrict__ out_w) {
    int t = blockIdx.x * 256 + threadIdx.x;
    if (t >= NEMB * DIM) return;
    int k = t >> 6;
    float nws = ws_in[t] * 0.99f + 0.01f * g_embsum[t];
    out_ws[t] = nws;
    float ncc = out_cc[k];
    float n = g_nsum;
    float sm = (ncc + 1e-5f) / (n + (float)NEMB * 1e-5f) * n;
    out_w[t] = nws / sm;
}

// ============================================================
__global__ void k_quant(const float* __restrict__ x, const float* __restrict__ out_w,
                        float* __restrict__ out_q) {
    int t = blockIdx.x * 256 + threadIdx.x;
    if (t >= N_ROWS * DIM) return;
    int n = t >> 6, d = t & 63;
    float q = out_w[g_idx[n] * DIM + d];
    out_q[t] = q;
    float df = q - x[t];
    float v = df * df;
#pragma unroll
    for (int m = 16; m >= 1; m >>= 1) v += __shfl_xor_sync(0xffffffffu, v, m);
    __shared__ float s[8];
    int wi = threadIdx.x >> 5, lane = threadIdx.x & 31;
    if (lane == 0) s[wi] = v;
    __syncthreads();
    if (threadIdx.x == 0) {
        float a = 0.f;
        for (int i = 0; i < 8; i++) a += s[i];
        atomicAdd(&g_loss, a);
    }
}

// ============================================================
__global__ void k_scalars(float* __restrict__ out) {
    out[OFF_LOSS] = 0.25f * g_loss * (1.0f / 2097152.0f);
    out[OFF_PERP] = expf(-g_plogp);
}

// ============================================================
extern "C" void kernel_launch(void* const* d_in, const int* in_sizes, int n_in,
                              void* d_out, int out_size) {
    const float* x  = (const float*)d_in[0];
    const float* w  = (const float*)d_in[1];
    const float* cc = (const float*)d_in[2];
    const float* ws = (const float*)d_in[3];
    float* out = (float*)d_out;

    cudaFuncSetAttribute(k_argmin_mma, cudaFuncAttributeMaxDynamicSharedMemorySize,
                         SMEM_BYTES);

    k_init      <<<2048, 256>>>();
    k_prep      <<<2048, 256>>>(w);
    k_enorm     <<<1024, 256>>>(w);
    k_argmin_mma<<<N_ROWS / RPB, NTHR, SMEM_BYTES>>>(x, out + OFF_IDX);
    k_fix       <<<128,  256>>>(x, w, out + OFF_IDX);
    k_scatter   <<<8192, 256>>>(x);
    k_cc        <<<32,   256>>>(cc, out + OFF_CC);
    k_weight    <<<2048, 256>>>(ws, out + OFF_CC, out + OFF_WS, out + OFF_W);
    k_quant     <<<8192, 256>>>(x, out + OFF_W, out + OFF_Q);
    k_scalars   <<<1, 1>>>(out);
}

// round 16
// speedup vs baseline: 2.0256x; 2.0256x over previous
#include <cuda_runtime.h>
#include <cuda_fp16.h>
#include <cstdint>
#include <math.h>

#define N_ROWS 32768
#define DIM    64
#define NEMB   8192

// ---- output layout (concatenated reference tuple, all float32) ----
#define OFF_Q    0
#define OFF_LOSS 2097152
#define OFF_IDX  2097153
#define OFF_PERP 2129921
#define OFF_W    2129922
#define OFF_CC   2654210
#define OFF_WS   2662402

// ---- argmin tiling ----
#define RPB   128            // rows per block (M)
#define CPC   128            // codes per chunk (N)
#define NCH   (NEMB/CPC)     // 64 chunks
#define NTHR  512            // 16 warps: 4(M) x 4(N)

// SMEM layout (bytes). Tiles: 128 rows x 128B (64 fp16), XOR-swizzled.
#define A_OFF      0                      // 2 x 16KB (h,m splits of x rows)
#define B_OFF      32768                  // 2 bufs x 2 x 16KB
#define SEN_OFF    98304                  // 2 x 512B
#define RED_OFF    99328                  // 128 rows x 4 warpcols x 8B
#define SMEM_BYTES 103424

// ---- device scratch ----
__device__ int   g_idx[N_ROWS];
__device__ float g_counts[NEMB];
__device__ float g_embsum[NEMB * DIM];
__device__ float g_enormh[NEMB];
__device__ float g_nsum;
__device__ float g_loss;
__device__ float g_plogp;
// pre-split codebook (2-term fp16 decomposition of w)
__device__ __half g_wh[NEMB * DIM];
__device__ __half g_wm[NEMB * DIM];

// ================= helpers =================
__device__ __forceinline__ uint32_t smem_u32_of(const void* p) {
    uint32_t a;
    asm("{ .reg .u64 t; cvta.to.shared.u64 t, %1; cvt.u32.u64 %0, t; }"
        : "=r"(a) : "l"(p));
    return a;
}
__device__ __forceinline__ void ldmx4(uint32_t& r0, uint32_t& r1, uint32_t& r2,
                                      uint32_t& r3, uint32_t a) {
    asm volatile("ldmatrix.sync.aligned.m8n8.x4.shared.b16 {%0,%1,%2,%3}, [%4];"
                 : "=r"(r0), "=r"(r1), "=r"(r2), "=r"(r3) : "r"(a));
}
__device__ __forceinline__ void mma16816(float& c0, float& c1, float& c2, float& c3,
                                         uint32_t a0, uint32_t a1, uint32_t a2, uint32_t a3,
                                         uint32_t b0, uint32_t b1) {
    asm volatile("mma.sync.aligned.m16n8k16.row.col.f32.f16.f16.f32 "
                 "{%0,%1,%2,%3}, {%4,%5,%6,%7}, {%8,%9}, {%0,%1,%2,%3};"
                 : "+f"(c0), "+f"(c1), "+f"(c2), "+f"(c3)
                 : "r"(a0), "r"(a1), "r"(a2), "r"(a3), "r"(b0), "r"(b1));
}
__device__ __forceinline__ void cp16(uint32_t dst, const void* src) {
    asm volatile("cp.async.cg.shared.global [%0], [%1], 16;" :: "r"(dst), "l"(src));
}
#define CP_COMMIT() asm volatile("cp.async.commit_group;" ::: "memory")
#define CP_WAIT0()  asm volatile("cp.async.wait_group 0;" ::: "memory")

__device__ __forceinline__ uint32_t pack_h2(__half a, __half b) {
    unsigned short ua = *(unsigned short*)&a, ub = *(unsigned short*)&b;
    return (uint32_t)ua | ((uint32_t)ub << 16);
}
__device__ __forceinline__ unsigned long long pack_key(float s, int j) {
    uint32_t u = __float_as_uint(s);
    u = (u & 0x80000000u) ? ~u : (u | 0x80000000u);   // order-preserving
    return ((unsigned long long)u << 32) | (uint32_t)(~j);  // bigger = better; ties -> smaller j
}

// ============================================================
__global__ void k_init() {
    int t = blockIdx.x * 256 + threadIdx.x;
    if (t < NEMB * DIM) g_embsum[t] = 0.f;
    if (t < NEMB)       g_counts[t] = 0.f;
    if (t == 0) { g_nsum = 0.f; g_loss = 0.f; g_plogp = 0.f; }
}

// 2-way fp16 split of the codebook
__global__ void k_prep(const float* __restrict__ w) {
    int t = blockIdx.x * 256 + threadIdx.x;
    float v = w[t];
    __half h = __float2half_rn(v);
    __half m = __float2half_rn(v - __half2float(h));
    g_wh[t] = h; g_wm[t] = m;
}

__global__ void k_enorm(const float* __restrict__ w) {
    int code = blockIdx.x * 8 + (threadIdx.x >> 5);
    int lane = threadIdx.x & 31;
    float a = w[code * DIM + lane];
    float b = w[code * DIM + 32 + lane];
    float s = a * a + b * b;
#pragma unroll
    for (int m = 16; m >= 1; m >>= 1) s += __shfl_xor_sync(0xffffffffu, s, m);
    if (lane == 0) g_enormh[code] = 0.5f * s;
}

// ============================================================
// fp16 2-split tensor-core argmin (products hh + hm + mh; the
// dropped mm term ~6e-7 is below the ~2e-6 f32 accumulation-order
// noise that both this kernel and the reference carry).
// 512 threads, warp grid 4Mx4N; A fragments register-resident.
// ============================================================
__device__ __forceinline__ void prefetch_chunk(uint32_t sb, int buf, int cbase, int tid) {
#pragma unroll
    for (int i = 0; i < 4; i++) {
        int u = tid + i * NTHR;               // 2 splits * 128 rows * 8 col16 = 2048
        int s = u >> 10;
        int rem = u & 1023;
        int row = rem >> 3, c16 = rem & 7;
        uint32_t dst = sb + B_OFF + buf * 32768 + s * 16384 +
                       row * 128 + (((uint32_t)(c16 ^ (row & 7))) << 4);
        const __half* wsp = (s == 0) ? g_wh : g_wm;
        cp16(dst, wsp + (size_t)(cbase + row) * 64 + c16 * 8);
    }
    if (tid >= NTHR - 32) {                   // sen: 128 floats = 32 x 16B
        int u = tid - (NTHR - 32);
        cp16(sb + SEN_OFF + buf * 512 + u * 16, g_enormh + cbase + u * 4);
    }
    CP_COMMIT();
}

__global__ void __launch_bounds__(NTHR, 1) k_argmin_mma(const float* __restrict__ x,
                                                        float* __restrict__ out_idxf) {
    extern __shared__ __align__(16) char smem[];
    uint32_t sb = smem_u32_of(smem);
    int tid = threadIdx.x;
    int wid = tid >> 5;
    int lid = tid & 31;
    int rowBase = blockIdx.x * RPB;

    int wr = wid & 3;          // M slab (32 rows)
    int wc = wid >> 2;         // N slab (32 codes)
    int Mbase = wr * 32;
    int Nbase = wc * 32;

    // ldmatrix lane geometry (same for A and B)
    int ri    = lid & 7;
    int mi    = lid >> 3;
    int rowIn = (mi & 1) * 8 + ri;   // row within 16-row tile
    int half  = mi >> 1;             // col16 half within tile
    uint32_t colk[4];
#pragma unroll
    for (int kt = 0; kt < 4; kt++) colk[kt] = (uint32_t)((kt * 2 + half) ^ ri) << 4;
    uint32_t aLane = sb + A_OFF + (uint32_t)(Mbase + rowIn) * 128;
    uint32_t bLane = sb + B_OFF + (uint32_t)(Nbase + rowIn) * 128;

    // kick off B prefetch for chunk 0
    prefetch_chunk(sb, 0, 0, tid);

    // ---- A fill: split 128x64 f32 rows into 2 swizzled fp16 tiles ----
#pragma unroll
    for (int i = 0; i < 2; i++) {
        int u = tid + i * NTHR;              // 128 rows * 8 col16 = 1024
        int row = u >> 3, c16 = u & 7;
        const float* src = x + (size_t)(rowBase + row) * 64 + c16 * 8;
        float4 f0 = *(const float4*)src;
        float4 f1 = *(const float4*)(src + 4);
        float v[8] = {f0.x, f0.y, f0.z, f0.w, f1.x, f1.y, f1.z, f1.w};
        __half hb[8], mb[8];
#pragma unroll
        for (int j = 0; j < 8; j++) {
            __half h = __float2half_rn(v[j]);
            hb[j] = h;
            mb[j] = __float2half_rn(v[j] - __half2float(h));
        }
        uint32_t off = (uint32_t)row * 128 + (((uint32_t)(c16 ^ (row & 7))) << 4);
        uint4 ph = make_uint4(pack_h2(hb[0], hb[1]), pack_h2(hb[2], hb[3]),
                              pack_h2(hb[4], hb[5]), pack_h2(hb[6], hb[7]));
        uint4 pm = make_uint4(pack_h2(mb[0], mb[1]), pack_h2(mb[2], mb[3]),
                              pack_h2(mb[4], mb[5]), pack_h2(mb[6], mb[7]));
        *(uint4*)(smem + A_OFF + off)         = ph;
        *(uint4*)(smem + A_OFF + 16384 + off) = pm;
    }
    __syncthreads();

    // ---- A fragments register-resident (2 splits x 2 mt x 4 kt x 4) ----
    uint32_t afr[2][2][4][4];
#pragma unroll
    for (int s = 0; s < 2; s++)
#pragma unroll
        for (int mt = 0; mt < 2; mt++)
#pragma unroll
            for (int kt = 0; kt < 4; kt++)
                ldmx4(afr[s][mt][kt][0], afr[s][mt][kt][1],
                      afr[s][mt][kt][2], afr[s][mt][kt][3],
                      aLane + s * 16384 + mt * 2048 + colk[kt]);

    CP_WAIT0();
    __syncthreads();

    float best[4];
    int   bi[4];
#pragma unroll
    for (int k = 0; k < 4; k++) { best[k] = -3.402823466e38f; bi[k] = 0; }

    for (int ch = 0; ch < NCH; ++ch) {
        int db = ch & 1;
        if (ch + 1 < NCH) prefetch_chunk(sb, db ^ 1, (ch + 1) * CPC, tid);

        uint32_t bB = bLane + db * 32768;
        const float* senp = (const float*)(smem + SEN_OFF + db * 512);

#pragma unroll
        for (int hh = 0; hh < 2; hh++) {     // 16-code N-half
            float acc[2][2][4];
#pragma unroll
            for (int mt = 0; mt < 2; mt++)
#pragma unroll
                for (int nt = 0; nt < 2; nt++)
#pragma unroll
                    for (int q = 0; q < 4; q++) acc[mt][nt][q] = 0.f;

            uint32_t bh = bB + hh * 2048;
            // B = h split: products hh (A=h) and mh (A=m)
#pragma unroll
            for (int kt = 0; kt < 4; kt++) {
                uint32_t b0, b1, b2, b3;
                ldmx4(b0, b1, b2, b3, bh + colk[kt]);
#pragma unroll
                for (int mt = 0; mt < 2; mt++) {
                    mma16816(acc[mt][0][0], acc[mt][0][1], acc[mt][0][2], acc[mt][0][3],
                             afr[0][mt][kt][0], afr[0][mt][kt][1],
                             afr[0][mt][kt][2], afr[0][mt][kt][3], b0, b2);
                    mma16816(acc[mt][1][0], acc[mt][1][1], acc[mt][1][2], acc[mt][1][3],
                             afr[0][mt][kt][0], afr[0][mt][kt][1],
                             afr[0][mt][kt][2], afr[0][mt][kt][3], b1, b3);
                }
#pragma unroll
                for (int mt = 0; mt < 2; mt++) {
                    mma16816(acc[mt][0][0], acc[mt][0][1], acc[mt][0][2], acc[mt][0][3],
                             afr[1][mt][kt][0], afr[1][mt][kt][1],
                             afr[1][mt][kt][2], afr[1][mt][kt][3], b0, b2);
                    mma16816(acc[mt][1][0], acc[mt][1][1], acc[mt][1][2], acc[mt][1][3],
                             afr[1][mt][kt][0], afr[1][mt][kt][1],
                             afr[1][mt][kt][2], afr[1][mt][kt][3], b1, b3);
                }
            }
            // B = m split: product hm (A=h)
#pragma unroll
            for (int kt = 0; kt < 4; kt++) {
                uint32_t b0, b1, b2, b3;
                ldmx4(b0, b1, b2, b3, bh + 16384 + colk[kt]);
#pragma unroll
                for (int mt = 0; mt < 2; mt++) {
                    mma16816(acc[mt][0][0], acc[mt][0][1], acc[mt][0][2], acc[mt][0][3],
                             afr[0][mt][kt][0], afr[0][mt][kt][1],
                             afr[0][mt][kt][2], afr[0][mt][kt][3], b0, b2);
                    mma16816(acc[mt][1][0], acc[mt][1][1], acc[mt][1][2], acc[mt][1][3],
                             afr[0][mt][kt][0], afr[0][mt][kt][1],
                             afr[0][mt][kt][2], afr[0][mt][kt][3], b1, b3);
                }
            }

            // ---- epilogue for this half: subtract 0.5||e||^2, argmax ----
            // ascending code order + strict > == lowest-index tie-break
#pragma unroll
            for (int nt = 0; nt < 2; nt++) {
                int nl = Nbase + hh * 16 + nt * 8 + (lid & 3) * 2;
                float2 se = *(const float2*)(senp + nl);
                int jb = ch * CPC + nl;
#pragma unroll
                for (int mt = 0; mt < 2; mt++) {
                    float s0 = acc[mt][nt][0] - se.x;
                    float s1 = acc[mt][nt][1] - se.y;
                    float s2 = acc[mt][nt][2] - se.x;
                    float s3 = acc[mt][nt][3] - se.y;
                    int r0 = mt * 2, r1 = mt * 2 + 1;
                    if (s0 > best[r0]) { best[r0] = s0; bi[r0] = jb; }
                    if (s1 > best[r0]) { best[r0] = s1; bi[r0] = jb + 1; }
                    if (s2 > best[r1]) { best[r1] = s2; bi[r1] = jb; }
                    if (s3 > best[r1]) { best[r1] = s3; bi[r1] = jb + 1; }
                }
            }
        }

        if (ch + 1 < NCH) CP_WAIT0();
        __syncthreads();
    }

    // ---- reduce: packed keys across quad lanes, then warps (wc) ----
    unsigned long long key[4];
#pragma unroll
    for (int rs = 0; rs < 4; rs++) key[rs] = pack_key(best[rs], bi[rs]);
#pragma unroll
    for (int m = 1; m <= 2; m <<= 1) {
#pragma unroll
        for (int rs = 0; rs < 4; rs++) {
            unsigned long long o = __shfl_xor_sync(0xffffffffu, key[rs], m);
            if (o > key[rs]) key[rs] = o;
        }
    }
    unsigned long long* red = (unsigned long long*)(smem + RED_OFF);
    if ((lid & 3) == 0) {
#pragma unroll
        for (int rs = 0; rs < 4; rs++) {
            int mt = rs >> 1, h = rs & 1;
            int row = Mbase + mt * 16 + (lid >> 2) + h * 8;   // row within block
            red[row * 4 + wc] = key[rs];
        }
    }
    __syncthreads();
    if (tid < RPB) {
        unsigned long long k = red[tid * 4];
#pragma unroll
        for (int c = 1; c < 4; c++) { unsigned long long o = red[tid * 4 + c]; if (o > k) k = o; }
        int b = (int)(uint32_t)(~(uint32_t)k);
        int row = rowBase + tid;
        g_idx[row] = b;
        out_idxf[row] = (float)b;
    }
}

// ============================================================
__global__ void k_scatter(const float* __restrict__ x) {
    int t = blockIdx.x * 256 + threadIdx.x;
    if (t >= N_ROWS * DIM) return;
    int n = t >> 6, d = t & 63;
    int idx = g_idx[n];
    atomicAdd(&g_embsum[idx * DIM + d], x[t]);
    if (d == 0) atomicAdd(&g_counts[idx], 1.0f);
}

// ============================================================
__global__ void k_cc(const float* __restrict__ cc_in, float* __restrict__ out_cc) {
    int k = blockIdx.x * 256 + threadIdx.x;
    float c = g_counts[k];
    float ncc = cc_in[k] * 0.99f + 0.01f * c;
    out_cc[k] = ncc;
    float p = c * (1.0f / 32768.0f);
    float pl = p * logf(p + 1e-10f);
#pragma unroll
    for (int m = 16; m >= 1; m >>= 1) {
        ncc += __shfl_xor_sync(0xffffffffu, ncc, m);
        pl  += __shfl_xor_sync(0xffffffffu, pl, m);
    }
    __shared__ float s1[8], s2[8];
    int wi = threadIdx.x >> 5, lane = threadIdx.x & 31;
    if (lane == 0) { s1[wi] = ncc; s2[wi] = pl; }
    __syncthreads();
    if (threadIdx.x == 0) {
        float a = 0.f, b = 0.f;
        for (int i = 0; i < 8; i++) { a += s1[i]; b += s2[i]; }
        atomicAdd(&g_nsum, a);
        atomicAdd(&g_plogp, b);
    }
}

// ============================================================
__global__ void k_weight(const float* __restrict__ ws_in, const float* __restrict__ out_cc,
                         float* __restrict__ out_ws, float* __restrict__ out_w) {
    int t = blockIdx.x * 256 + threadIdx.x;
    if (t >= NEMB * DIM) return;
    int k = t >> 6;
    float nws = ws_in[t] * 0.99f + 0.01f * g_embsum[t];
    out_ws[t] = nws;
    float ncc = out_cc[k];
    float n = g_nsum;
    float sm = (ncc + 1e-5f) / (n + (float)NEMB * 1e-5f) * n;
    out_w[t] = nws / sm;
}

// ============================================================
__global__ void k_quant(const float* __restrict__ x, const float* __restrict__ out_w,
                        float* __restrict__ out_q) {
    int t = blockIdx.x * 256 + threadIdx.x;
    if (t >= N_ROWS * DIM) return;
    int n = t >> 6, d = t & 63;
    float q = out_w[g_idx[n] * DIM + d];
    out_q[t] = q;
    float df = q - x[t];
    float v = df * df;
#pragma unroll
    for (int m = 16; m >= 1; m >>= 1) v += __shfl_xor_sync(0xffffffffu, v, m);
    __shared__ float s[8];
    int wi = threadIdx.x >> 5, lane = threadIdx.x & 31;
    if (lane == 0) s[wi] = v;
    __syncthreads();
    if (threadIdx.x == 0) {
        float a = 0.f;
        for (int i = 0; i < 8; i++) a += s[i];
        atomicAdd(&g_loss, a);
    }
}

// ============================================================
__global__ void k_scalars(float* __restrict__ out) {
    out[OFF_LOSS] = 0.25f * g_loss * (1.0f / 2097152.0f);
    out[OFF_PERP] = expf(-g_plogp);
}

// ============================================================
extern "C" void kernel_launch(void* const* d_in, const int* in_sizes, int n_in,
                              void* d_out, int out_size) {
    const float* x  = (const float*)d_in[0];
    const float* w  = (const float*)d_in[1];
    const float* cc = (const float*)d_in[2];
    const float* ws = (const float*)d_in[3];
    float* out = (float*)d_out;

    cudaFuncSetAttribute(k_argmin_mma, cudaFuncAttributeMaxDynamicSharedMemorySize,
                         SMEM_BYTES);

    k_init      <<<2048, 256>>>();
    k_prep      <<<2048, 256>>>(w);
    k_enorm     <<<1024, 256>>>(w);
    k_argmin_mma<<<N_ROWS / RPB, NTHR, SMEM_BYTES>>>(x, out + OFF_IDX);
    k_scatter   <<<8192, 256>>>(x);
    k_cc        <<<32,   256>>>(cc, out + OFF_CC);
    k_weight    <<<2048, 256>>>(ws, out + OFF_CC, out + OFF_WS, out + OFF_W);
    k_quant     <<<8192, 256>>>(x, out + OFF_W, out + OFF_Q);
    k_scalars   <<<1, 1>>>(out);
}